// round 6
// baseline (speedup 1.0000x reference)
#include <cuda_runtime.h>
#include <cuda_bf16.h>

// Problem constants
#define B_   8
#define LQ_  512
#define LK_  512
#define D_   512
#define H_   128
#define M_   (B_ * LQ_)

// Scratch + sync state (no cudaMalloc allowed)
__device__ float g_Q[M_ * H_];
__device__ float g_K[M_ * H_];
__device__ int   g_done[B_];   // per-batch proj-tile counters (target 32)

__device__ __forceinline__ float fast_tanh(float x) {
    float y;
    asm("tanh.approx.f32 %0, %1;" : "=f"(y) : "f"(x));
    return y;
}
__device__ __forceinline__ unsigned long long fma_f32x2(
    unsigned long long a, unsigned long long b, unsigned long long c) {
    unsigned long long d;
    asm("fma.rn.f32x2 %0, %1, %2, %3;" : "=l"(d) : "l"(a), "l"(b), "l"(c));
    return d;
}
__device__ __forceinline__ unsigned long long pack2(float lo, float hi) {
    unsigned long long p;
    asm("mov.b64 %0, {%1, %2};" : "=l"(p) : "f"(lo), "f"(hi));
    return p;
}
__device__ __forceinline__ void unpack2(unsigned long long p, float& lo, float& hi) {
    asm("mov.b64 {%0, %1}, %2;" : "=f"(lo), "=f"(hi) : "l"(p));
}

// ---------------------------------------------------------------------------
// Fused kernel.
//   bids [0, 256):    proj tiles, BM=32 (16 outputs/thread -> low regs).
//                     Batch-major: b = bid/32; batch 0 finishes first.
//   bids [256, 1280): score tiles (32q x 64k), spin on g_done[b] == 32.
// Proj bids all fit in wave 1 (148 SMs x occ>=2 >= 256), so spinners can
// never starve the producers. Proj is deliberately latency-exposed (no
// prefetch) — co-resident MUFU-bound score warps hide it.
// ---------------------------------------------------------------------------
#define PROJ_BIDS 256
#define PBM 32
#define PBK 16
#define TQ 32
#define TK 64
#define TILES_PER_BATCH 32   // (512/32) tiles x 2 matrices

union SmemU {
    struct { float As[PBK][PBM + 8]; float Bs[PBK][H_]; } p;           // 10.6 KB
    struct { float sq[TQ][65]; float sk[TK][65]; float swv[H_]; } s;   // 25.5 KB
};

__global__ void init_kernel() {
    if (threadIdx.x < B_) g_done[threadIdx.x] = 0;
}

__global__ __launch_bounds__(256) void fused_kernel(
    const float* __restrict__ qs, const float* __restrict__ ks,
    const float* __restrict__ Wq, const float* __restrict__ Wk,
    const float* __restrict__ wv, float* __restrict__ out)
{
    __shared__ SmemU u;
    int bid = blockIdx.x;
    int tid = threadIdx.x;

    if (bid < PROJ_BIDS) {
        // ----------------- projection tile (BM=32, BK=16, BN=128) ---------
        int b   = bid >> 5;                  // batch
        int r   = bid & 31;
        int mat = r >> 4;                    // 0 = Q, 1 = K
        int t   = r & 15;                    // 32-row tile within batch
        const float* __restrict__ X = mat ? ks : qs;
        const float* __restrict__ W = mat ? Wk : Wq;
        float* __restrict__ Y       = mat ? g_K : g_Q;
        int row0 = b * LQ_ + t * PBM;

        int tx = tid & 31;                   // col group (4 cols)
        int ty = tid >> 5;                   // row group (4 rows)
        int br = tid >> 5, bc4 = tid & 31;   // B loads: rows br, br+8

        unsigned long long acc2[2][4];
#pragma unroll
        for (int i = 0; i < 2; i++)
#pragma unroll
            for (int j = 0; j < 4; j++) acc2[i][j] = 0ull;

        for (int k0 = 0; k0 < D_; k0 += PBK) {
            // A tile 32x16 = 128 float4: threads 0..127
            if (tid < 128) {
                int ar = tid >> 2, ac4 = tid & 3;
                float4 v = *(const float4*)(X + (size_t)(row0 + ar) * D_ + k0 + ac4 * 4);
                u.p.As[ac4 * 4 + 0][ar] = v.x;
                u.p.As[ac4 * 4 + 1][ar] = v.y;
                u.p.As[ac4 * 4 + 2][ar] = v.z;
                u.p.As[ac4 * 4 + 3][ar] = v.w;
            }
            // B tile 16x128 = 512 float4: 2 per thread
            *(float4*)(&u.p.Bs[br][bc4 * 4]) =
                *(const float4*)(W + (size_t)(k0 + br) * H_ + bc4 * 4);
            *(float4*)(&u.p.Bs[br + 8][bc4 * 4]) =
                *(const float4*)(W + (size_t)(k0 + br + 8) * H_ + bc4 * 4);
            __syncthreads();

#pragma unroll
            for (int kk = 0; kk < PBK; ++kk) {
                ulonglong2 a01 = *(const ulonglong2*)(&u.p.As[kk][ty * 4]);
                float4 bv = *(const float4*)(&u.p.Bs[kk][tx * 4]);
                unsigned long long bd[4] = {
                    pack2(bv.x, bv.x), pack2(bv.y, bv.y),
                    pack2(bv.z, bv.z), pack2(bv.w, bv.w)};
                acc2[0][0] = fma_f32x2(a01.x, bd[0], acc2[0][0]);
                acc2[0][1] = fma_f32x2(a01.x, bd[1], acc2[0][1]);
                acc2[0][2] = fma_f32x2(a01.x, bd[2], acc2[0][2]);
                acc2[0][3] = fma_f32x2(a01.x, bd[3], acc2[0][3]);
                acc2[1][0] = fma_f32x2(a01.y, bd[0], acc2[1][0]);
                acc2[1][1] = fma_f32x2(a01.y, bd[1], acc2[1][1]);
                acc2[1][2] = fma_f32x2(a01.y, bd[2], acc2[1][2]);
                acc2[1][3] = fma_f32x2(a01.y, bd[3], acc2[1][3]);
            }
            __syncthreads();
        }

        // Epilogue: rows row0 + ty*4 + 2i (+1 in hi), cols tx*4..+3
#pragma unroll
        for (int i = 0; i < 2; i++) {
            float lo[4], hi[4];
#pragma unroll
            for (int j = 0; j < 4; j++) unpack2(acc2[i][j], lo[j], hi[j]);
            size_t r0 = (size_t)(row0 + ty * 4 + 2 * i) * H_ + tx * 4;
            *(float4*)(Y + r0)      = make_float4(lo[0], lo[1], lo[2], lo[3]);
            *(float4*)(Y + r0 + H_) = make_float4(hi[0], hi[1], hi[2], hi[3]);
        }

        __syncthreads();
        __threadfence();
        if (tid == 0) atomicAdd(&g_done[b], 1);

    } else {
        // ----------------- score tile (32q x 64k) -------------------------
        int s  = bid - PROJ_BIDS;
        int b  = s >> 7;
        int w  = s & 127;
        int q0 = (w >> 3) * TQ;
        int k0 = (w & 7) * TK;

        if (tid == 0) {
            while (*(volatile int*)&g_done[b] < TILES_PER_BATCH) __nanosleep(100);
        }
        __syncthreads();
        __threadfence();

        const float* Qb = g_Q + (size_t)(b * LQ_ + q0) * H_;
        const float* Kb = g_K + (size_t)(b * LK_ + k0) * H_;

        if (tid < H_) u.s.swv[tid] = wv[tid];

        int tx = tid & 15;
        int ty = tid >> 4;

        float acc[2][4];
#pragma unroll
        for (int i = 0; i < 2; i++)
#pragma unroll
            for (int j = 0; j < 4; j++) acc[i][j] = 0.f;

#pragma unroll
        for (int half = 0; half < 2; ++half) {
            __syncthreads();
            for (int i = tid; i < 512; i += 256) {
                int r = i >> 4, c4 = i & 15;
                float4 v = *(const float4*)(Qb + r * H_ + half * 64 + c4 * 4);
                float* dq = &u.s.sq[r][c4 * 4];
                dq[0] = v.x; dq[1] = v.y; dq[2] = v.z; dq[3] = v.w;
            }
            for (int i = tid; i < 1024; i += 256) {
                int r = i >> 4, c4 = i & 15;
                float4 wv4 = *(const float4*)(Kb + r * H_ + half * 64 + c4 * 4);
                float* dk = &u.s.sk[r][c4 * 4];
                dk[0] = wv4.x; dk[1] = wv4.y; dk[2] = wv4.z; dk[3] = wv4.w;
            }
            __syncthreads();

#pragma unroll 4
            for (int h = 0; h < 64; ++h) {
                float wvh = u.s.swv[half * 64 + h];
                float qv[2], kv[4];
#pragma unroll
                for (int i = 0; i < 2; i++) qv[i] = u.s.sq[ty + 16 * i][h];
#pragma unroll
                for (int j = 0; j < 4; j++) kv[j] = u.s.sk[tx + 16 * j][h];
#pragma unroll
                for (int i = 0; i < 2; i++)
#pragma unroll
                    for (int j = 0; j < 4; j++)
                        acc[i][j] = fmaf(wvh, fast_tanh(qv[i] + kv[j]), acc[i][j]);
            }
        }

        float* ob = out + ((size_t)b * LQ_ + q0) * LK_ + k0;
#pragma unroll
        for (int i = 0; i < 2; i++)
#pragma unroll
            for (int j = 0; j < 4; j++)
                ob[(size_t)(ty + 16 * i) * LK_ + tx + 16 * j] = acc[i][j];
    }
}

// ---------------------------------------------------------------------------

extern "C" void kernel_launch(void* const* d_in, const int* in_sizes, int n_in,
                              void* d_out, int out_size)
{
    const float* qs = (const float*)d_in[0];   // [8,512,512]
    const float* ks = (const float*)d_in[1];   // [8,512,512]
    const float* Wq = (const float*)d_in[2];   // [512,128]
    const float* Wk = (const float*)d_in[3];   // [512,128]
    const float* wv = (const float*)d_in[4];   // [128]
    float* out = (float*)d_out;                // [8,512,512]

    init_kernel<<<1, 32>>>();
    fused_kernel<<<PROJ_BIDS + B_ * (LQ_ / TQ) * (LK_ / TK), 256>>>(
        qs, ks, Wq, Wk, wv, out);
}